// round 16
// baseline (speedup 1.0000x reference)
#include <cuda_runtime.h>
#include <cuda_fp16.h>
#include <math.h>
#include <stdint.h>

#define NN 8192
#define DIN 512
#define DOUT 256

// ---------------- scratch (static device memory; no allocation) ----------------
__device__ __half g_xh[NN * DIN];           // x in fp16
__device__ __half g_wh[DOUT * DIN];         // W in fp16
__device__ __half g_hT[DOUT * NN];          // h transposed [n][j], fp16 (MMA B operand)
__device__ float g_b1[DIN];                 // W^T a1
__device__ float g_b2[DIN];                 // W^T a2
__device__ float g_f1[NN];
__device__ float g_f2[NN];
__device__ float g_u[NN];                   // exp(f2)
__device__ float g_v[NN];                   // exp(0.01*f2)
__device__ unsigned g_m2key;                // monotone-key max of f2
__device__ float g_O[2 * NN * DOUT];        // partial O per j-half (16 MB)
__device__ float g_l[2 * NN];               // partial softmax denominators

// ---------------- helpers ----------------
__device__ __forceinline__ float fexp(float x) {
    float j = fmaf(x, 1.4426950408889634f, 12582912.0f);
    float n = j - 12582912.0f;
    float f = fmaf(n, -0.693359375f, x);
    f = fmaf(n, 2.1219444e-4f, f);
    float r = fmaf(f, 0.041666668f, 0.16666667f);
    r = fmaf(r, f, 0.5f);
    r = fmaf(r, f, 1.0f);
    r = fmaf(r, f, 1.0f);
    int sc = __float_as_int(j) << 23;
    return __int_as_float(__float_as_int(r) + sc);
}

__device__ __forceinline__ void mma_f16(float* d, const unsigned* a,
                                        unsigned b0, unsigned b1) {
    asm volatile(
        "mma.sync.aligned.m16n8k16.row.col.f32.f16.f16.f32 "
        "{%0,%1,%2,%3}, {%4,%5,%6,%7}, {%8,%9}, {%0,%1,%2,%3};\n"
        : "+f"(d[0]), "+f"(d[1]), "+f"(d[2]), "+f"(d[3])
        : "r"(a[0]), "r"(a[1]), "r"(a[2]), "r"(a[3]), "r"(b0), "r"(b1));
}

__device__ __forceinline__ void ldsm_x4(unsigned& r0, unsigned& r1,
                                        unsigned& r2, unsigned& r3, uint32_t addr) {
    asm volatile("ldmatrix.sync.aligned.m8n8.x4.shared.b16 {%0,%1,%2,%3}, [%4];"
                 : "=r"(r0), "=r"(r1), "=r"(r2), "=r"(r3) : "r"(addr));
}

__device__ __forceinline__ void cp_async16(uint32_t saddr, const void* gptr) {
    asm volatile("cp.async.cg.shared.global [%0], [%1], 16;\n"
                 :: "r"(saddr), "l"(gptr));
}
#define CP_COMMIT() asm volatile("cp.async.commit_group;\n" ::: "memory")
#define CP_WAIT(N)  asm volatile("cp.async.wait_group %0;\n" :: "n"(N) : "memory")

__device__ __forceinline__ unsigned f2key(float x) {
    unsigned u = __float_as_uint(x);
    return ((int)u >= 0) ? (u | 0x80000000u) : ~u;
}

// ---------------- kernel 0: convert x, W to fp16 ----------------
__global__ __launch_bounds__(256) void k_cvt(const float* __restrict__ x,
                                             const float* __restrict__ W) {
    int b = blockIdx.x;
    const float* src;
    __half* dst;
    size_t v;
    if (b < 4096) { src = x; dst = g_xh; v = (size_t)b * 256 + threadIdx.x; }
    else          { src = W; dst = g_wh; v = (size_t)(b - 4096) * 256 + threadIdx.x; }
    float4 f = __ldg((const float4*)src + v);
    union { __half2 h[2]; uint2 u; } pk;
    pk.h[0] = __floats2half2_rn(f.x, f.y);
    pk.h[1] = __floats2half2_rn(f.z, f.w);
    *(uint2*)&dst[v * 4] = pk.u;
}

// ---------------- kernel 1: hT = W @ x^T via fp16 mma + cp.async pipeline -----
#define KH_S 72
#define KH_BUF (128 * KH_S)
#define KH_SMEM_BYTES (4 * KH_BUF * 2)       // 73728
__global__ __launch_bounds__(512) void k_h() {
    extern __shared__ __align__(16) __half kh_sm[];
    __half* sW = kh_sm;
    __half* sX = kh_sm + 2 * KH_BUF;
    const int tid = threadIdx.x;
    const int lane = tid & 31, w = tid >> 5;
    const int wm = w >> 2, wn = w & 3;
    const int g = lane >> 2, tq = lane & 3;
    const int n0 = blockIdx.x * 128, j0 = blockIdx.y * 128;
    const uint32_t swb = (uint32_t)__cvta_generic_to_shared(sW);
    const uint32_t sxb = (uint32_t)__cvta_generic_to_shared(sX);

    float acc[2][4][4];
#pragma unroll
    for (int mt = 0; mt < 2; mt++)
#pragma unroll
        for (int jb = 0; jb < 4; jb++)
#pragma unroll
            for (int q = 0; q < 4; q++) acc[mt][jb][q] = 0.0f;

    const int aoff = (wm * 32 + (lane & 15)) * KH_S + (lane >> 4) * 8;
    const int boff = (wn * 32 + (lane & 7) + ((lane & 16) ? 8 : 0)) * KH_S +
                     ((lane >> 3) & 1) * 8;

    auto issue = [&](int c) {
        int k0 = c * 64;
        int bsel = (c & 1) * KH_BUF;
#pragma unroll
        for (int q = 0; q < 2; q++) {
            int v = tid + q * 512;
            int r = v >> 3, ck = (v & 7) << 3;
            cp_async16(swb + (bsel + r * KH_S + ck) * 2,
                       g_wh + (size_t)(n0 + r) * DIN + k0 + ck);
            cp_async16(sxb + (bsel + r * KH_S + ck) * 2,
                       g_xh + (size_t)(j0 + r) * DIN + k0 + ck);
        }
    };

    issue(0); CP_COMMIT();
    for (int c = 0; c < 8; c++) {
        __syncthreads();
        if (c < 7) { issue(c + 1); CP_COMMIT(); }
        if (c < 7) { CP_WAIT(1); } else { CP_WAIT(0); }
        __syncthreads();
        const uint32_t aB = swb + ((c & 1) * KH_BUF + aoff) * 2;
        const uint32_t bB = sxb + ((c & 1) * KH_BUF + boff) * 2;
#pragma unroll
        for (int ks = 0; ks < 4; ks++) {
            unsigned A0[4], A1[4];
            ldsm_x4(A0[0], A0[1], A0[2], A0[3], aB + (ks * 16) * 2);
            ldsm_x4(A1[0], A1[1], A1[2], A1[3], aB + (16 * KH_S + ks * 16) * 2);
#pragma unroll
            for (int jp = 0; jp < 2; jp++) {
                unsigned B[4];
                ldsm_x4(B[0], B[1], B[2], B[3], bB + (jp * 16 * KH_S + ks * 16) * 2);
                mma_f16(acc[0][2 * jp], A0, B[0], B[1]);
                mma_f16(acc[0][2 * jp + 1], A0, B[2], B[3]);
                mma_f16(acc[1][2 * jp], A1, B[0], B[1]);
                mma_f16(acc[1][2 * jp + 1], A1, B[2], B[3]);
            }
        }
    }
#pragma unroll
    for (int mt = 0; mt < 2; mt++) {
        int n = n0 + wm * 32 + mt * 16 + g;
#pragma unroll
        for (int jb = 0; jb < 4; jb++) {
            int j = j0 + wn * 32 + jb * 8 + 2 * tq;
            *(__half2*)&g_hT[(size_t)n * NN + j] =
                __floats2half2_rn(acc[mt][jb][0], acc[mt][jb][1]);
            *(__half2*)&g_hT[(size_t)(n + 8) * NN + j] =
                __floats2half2_rn(acc[mt][jb][2], acc[mt][jb][3]);
        }
    }
}

// ---------------- kernel 2a: b1 = W^T a1, b2 = W^T a2; init m2key -------------
__global__ __launch_bounds__(512) void k_vec(const float* __restrict__ W,
                                             const float* __restrict__ a1,
                                             const float* __restrict__ a2) {
    __shared__ float as[DOUT];
    const float* a = blockIdx.x ? a2 : a1;
    float* out = blockIdx.x ? g_b2 : g_b1;
    int tid = threadIdx.x;
    if (blockIdx.x == 0 && tid == 0) g_m2key = 0u;   // reset (graph replays)
    if (tid < DOUT) as[tid] = a[tid];
    __syncthreads();
    float s = 0.0f;
#pragma unroll 16
    for (int i = 0; i < DOUT; i++)
        s = fmaf(__ldg(W + (size_t)i * DIN + tid), as[i], s);
    out[tid] = s;
}

// ---------------- kernel 2b: f1/f2 (fp32) + u=exp(f2), v=exp(.01 f2) + max ----
__global__ __launch_bounds__(256) void k_f12(const float* __restrict__ x) {
    __shared__ float b1s[DIN], b2s[DIN];
    __shared__ float mx[8];
    int tid = threadIdx.x;
    b1s[tid] = g_b1[tid]; b1s[tid + 256] = g_b1[tid + 256];
    b2s[tid] = g_b2[tid]; b2s[tid + 256] = g_b2[tid + 256];
    __syncthreads();
    int w = tid >> 5, lane = tid & 31;
    int row = blockIdx.x * 8 + w;
    const float* xr = x + (size_t)row * DIN;
    float s1 = 0.0f, s2 = 0.0f;
#pragma unroll
    for (int q = 0; q < 4; q++) {
        float4 xv = __ldg((const float4*)(xr + q * 128 + lane * 4));
        int c = q * 128 + lane * 4;
        s1 = fmaf(xv.x, b1s[c], fmaf(xv.y, b1s[c + 1],
             fmaf(xv.z, b1s[c + 2], fmaf(xv.w, b1s[c + 3], s1))));
        s2 = fmaf(xv.x, b2s[c], fmaf(xv.y, b2s[c + 1],
             fmaf(xv.z, b2s[c + 2], fmaf(xv.w, b2s[c + 3], s2))));
    }
#pragma unroll
    for (int off = 16; off >= 1; off >>= 1) {
        s1 += __shfl_xor_sync(0xffffffffu, s1, off);
        s2 += __shfl_xor_sync(0xffffffffu, s2, off);
    }
    if (lane == 0) {
        g_f1[row] = s1; g_f2[row] = s2;
        g_u[row] = fexp(s2);
        g_v[row] = fexp(0.01f * s2);
        mx[w] = s2;
    }
    __syncthreads();
    if (tid == 0) {
        float m = mx[0];
#pragma unroll
        for (int i = 1; i < 8; i++) m = fmaxf(m, mx[i]);
        atomicMax(&g_m2key, f2key(m));       // order-independent -> deterministic
    }
}

// ---------------- kernel 3: fused softmax-numerator @ h, intra-warp pipelined -
// grid (2, 64), 512 threads, 16 warps (4m x 4n). Double-buffered sP/sHT; ONE
// barrier per tile. Loop body fuses MMA(t) (buffer b) with P(t+1) (buffer b^1)
// in one instruction stream so each warp's tensor-latency bubbles are filled by
// its own fma work. Rank-1 factored P (no exp in hot loop), p in (0,1].
#define SPH 136
#define SP_HALFS   (128 * SPH)
#define SHT_HALFS  (256 * SPH)
#define F1_BYTEOFF (4 * SP_HALFS + 4 * SHT_HALFS)
#define SMEM_BYTES (F1_BYTEOFF + 3 * 512 + 128)
__global__ __launch_bounds__(512, 1) void k_attn(const float* __restrict__ adj) {
    extern __shared__ __align__(16) __half smh[];
    float* f1s = (float*)((char*)smh + F1_BYTEOFF);
    float* sA  = f1s + 128;
    float* sB  = f1s + 256;

    const int tid = threadIdx.x;
    const int jh = blockIdx.x, rb = blockIdx.y;
    const int lane = tid & 31, w = tid >> 5;
    const int wm = w >> 2, wn = w & 3;
    const int g = lane >> 2, tq = lane & 3;

    unsigned mk = g_m2key;
    const float m2 = (mk & 0x80000000u) ? __uint_as_float(mk & 0x7FFFFFFFu)
                                        : __uint_as_float(~mk);
    if (tid < 128) {
        float f1 = g_f1[rb * 128 + tid];
        float zc = f1 + m2;
        float c = fmaxf(zc, 0.01f * zc);     // row shift (same both halves)
        f1s[tid] = f1;
        sA[tid] = fexp(f1 - c);
        sB[tid] = fexp(fmaf(0.01f, f1, -c));
    }
    __syncthreads();

    float acc[2][8][4];
#pragma unroll
    for (int mt = 0; mt < 2; mt++)
#pragma unroll
        for (int nb = 0; nb < 8; nb++)
#pragma unroll
            for (int q = 0; q < 4; q++) acc[mt][nb][q] = 0.0f;

    float lacc[8];
#pragma unroll
    for (int i = 0; i < 8; i++) lacc[i] = 0.0f;

    const float* adjb = adj + (size_t)(rb * 128) * NN;
    const uint32_t smbase = (uint32_t)__cvta_generic_to_shared(smh);

    const int aoff = (wm * 32 + (lane & 15)) * SPH + (lane >> 4) * 8;
    const int boff = (wn * 64 + (lane & 7) + ((lane & 16) ? 8 : 0)) * SPH +
                     ((lane >> 3) & 1) * 8;

    // H-tile staging into buffer bb
    auto stage_H = [&](int jt, int bb) {
        const __half* hsrc = g_hT + jh * 4096 + jt * 128;
        const uint32_t sht_b = smbase + (2 * SP_HALFS + bb * SHT_HALFS) * 2;
#pragma unroll
        for (int i = 0; i < 8; i++) {
            int v = tid + i * 512;
            int n = v >> 4;
            int c = (v & 15) << 3;
            cp_async16(sht_b + (n * SPH + c) * 2, hsrc + (size_t)n * NN + c);
        }
    };

    // ---- prologue: stage H(0), compute P(0) into buffer 0 ----
    stage_H(0, 0); CP_COMMIT();
    {
        const int j0 = jh * 4096;
        float4 f2v = __ldg((const float4*)(g_f2 + j0 + 4 * lane));
        float4 uv  = __ldg((const float4*)(g_u  + j0 + 4 * lane));
        float4 vv  = __ldg((const float4*)(g_v  + j0 + 4 * lane));
        __half* sP0 = smh;
#pragma unroll
        for (int i = 0; i < 8; i++) {
            int r = w + 16 * i;
            float4 av = __ldg((const float4*)(adjb + (size_t)r * NN + j0 + 4 * lane));
            float f1v = f1s[r], ai = sA[r], bi = sB[r];
            float p0 = ((f1v + f2v.x >= 0.0f) ? ai * uv.x : bi * vv.x) * av.x;
            float p1 = ((f1v + f2v.y >= 0.0f) ? ai * uv.y : bi * vv.y) * av.y;
            float p2 = ((f1v + f2v.z >= 0.0f) ? ai * uv.z : bi * vv.z) * av.z;
            float p3 = ((f1v + f2v.w >= 0.0f) ? ai * uv.w : bi * vv.w) * av.w;
            __half2 h01 = __floats2half2_rn(p0, p1);
            __half2 h23 = __floats2half2_rn(p2, p3);
            union { __half2 h2[2]; uint2 u; } pk;
            pk.h2[0] = h01; pk.h2[1] = h23;
            *(uint2*)&sP0[r * SPH + 4 * lane] = pk.u;
            float2 q01 = __half22float2(h01);
            float2 q23 = __half22float2(h23);
            lacc[i] += (q01.x + q01.y) + (q23.x + q23.y);
        }
    }

    for (int jt = 0; jt < 32; jt++) {
        const int b = jt & 1;
        const bool more = (jt < 31);
        CP_WAIT(0);                          // H(t) landed
        __syncthreads();                     // P(t)/H(t) visible; MMA(t-1) done

        if (more) { stage_H(jt + 1, b ^ 1); CP_COMMIT(); }

        // P(t+1) per-lane inputs (first adj batch; MLP=4)
        const int j1 = jh * 4096 + (jt + 1) * 128;
        float4 f2v, uv, vv, av[8];
        if (more) {
            f2v = __ldg((const float4*)(g_f2 + j1 + 4 * lane));
            uv  = __ldg((const float4*)(g_u  + j1 + 4 * lane));
            vv  = __ldg((const float4*)(g_v  + j1 + 4 * lane));
#pragma unroll
            for (int i = 0; i < 4; i++)
                av[i] = __ldg((const float4*)(adjb + (size_t)(w + 16 * i) * NN + j1 + 4 * lane));
        }
        __half* sPn = smh + (b ^ 1) * SP_HALFS;
        const uint32_t aB = smbase + (b * SP_HALFS + aoff) * 2;
        const uint32_t bB = smbase + (2 * SP_HALFS + b * SHT_HALFS + boff) * 2;

        // ---- fused: MMA chunk s (tile t) + P chunk s-2 (tile t+1) ----
#pragma unroll
        for (int s = 0; s < 10; s++) {
            if (s < 8) {
                unsigned A0[4], A1[4];
                ldsm_x4(A0[0], A0[1], A0[2], A0[3], aB + (s * 16) * 2);
                ldsm_x4(A1[0], A1[1], A1[2], A1[3], aB + (16 * SPH + s * 16) * 2);
#pragma unroll
                for (int np = 0; np < 4; np++) {
                    unsigned B[4];
                    ldsm_x4(B[0], B[1], B[2], B[3], bB + (np * 16 * SPH + s * 16) * 2);
                    mma_f16(acc[0][2 * np], A0, B[0], B[1]);
                    mma_f16(acc[0][2 * np + 1], A0, B[2], B[3]);
                    mma_f16(acc[1][2 * np], A1, B[0], B[1]);
                    mma_f16(acc[1][2 * np + 1], A1, B[2], B[3]);
                }
            }
            if (s == 3 && more) {            // second adj batch (2-3 chunks ahead of use)
#pragma unroll
                for (int i = 4; i < 8; i++)
                    av[i] = __ldg((const float4*)(adjb + (size_t)(w + 16 * i) * NN + j1 + 4 * lane));
            }
            if (s >= 2 && more) {
                int i = s - 2;
                int r = w + 16 * i;
                float f1v = f1s[r], ai = sA[r], bi = sB[r];
                float p0 = ((f1v + f2v.x >= 0.0f) ? ai * uv.x : bi * vv.x) * av[i].x;
                float p1 = ((f1v + f2v.y >= 0.0f) ? ai * uv.y : bi * vv.y) * av[i].y;
                float p2 = ((f1v + f2v.z >= 0.0f) ? ai * uv.z : bi * vv.z) * av[i].z;
                float p3 = ((f1v + f2v.w >= 0.0f) ? ai * uv.w : bi * vv.w) * av[i].w;
                __half2 h01 = __floats2half2_rn(p0, p1);
                __half2 h23 = __floats2half2_rn(p2, p3);
                union { __half2 h2[2]; uint2 u; } pk;
                pk.h2[0] = h01; pk.h2[1] = h23;
                *(uint2*)&sPn[r * SPH + 4 * lane] = pk.u;
                float2 q01 = __half22float2(h01);
                float2 q23 = __half22float2(h23);
                lacc[i] += (q01.x + q01.y) + (q23.x + q23.y);
            }
        }
    }

    // ---- final row-sum reduce + store partial l ----
#pragma unroll
    for (int i = 0; i < 8; i++) {
        float s = lacc[i];
#pragma unroll
        for (int off = 16; off >= 1; off >>= 1)
            s += __shfl_xor_sync(0xffffffffu, s, off);
        if (lane == 0) g_l[jh * NN + rb * 128 + w + 16 * i] = s;
    }

    // ---- epilogue: partial O ----
    float* Op = g_O + (size_t)jh * NN * DOUT;
#pragma unroll
    for (int mt = 0; mt < 2; mt++) {
        int row0 = rb * 128 + wm * 32 + mt * 16 + g;
#pragma unroll
        for (int nb = 0; nb < 8; nb++) {
            int col = wn * 64 + nb * 8 + tq * 2;
            *(float2*)&Op[(size_t)row0 * DOUT + col] =
                make_float2(acc[mt][nb][0], acc[mt][nb][1]);
            *(float2*)&Op[(size_t)(row0 + 8) * DOUT + col] =
                make_float2(acc[mt][nb][2], acc[mt][nb][3]);
        }
    }
}

// ---------------- kernel 4: combine halves, divide, elu ----------------
__global__ __launch_bounds__(256) void k_out(float* __restrict__ out) {
    int idx = blockIdx.x * 256 + threadIdx.x;
    int row = idx >> 8;
    float linv = 1.0f / (g_l[row] + g_l[NN + row]);
    float o = (g_O[idx] + g_O[NN * DOUT + idx]) * linv;
    out[idx] = (o > 0.0f) ? o : expm1f(o);
}

// ---------------- launch ----------------
extern "C" void kernel_launch(void* const* d_in, const int* in_sizes, int n_in,
                              void* d_out, int out_size) {
    const float* x   = (const float*)d_in[0];   // [8192, 512]
    const float* adj = (const float*)d_in[1];   // [8192, 8192]
    const float* W   = (const float*)d_in[2];   // [256, 512]
    const float* a1  = (const float*)d_in[3];   // [256]
    const float* a2  = (const float*)d_in[4];   // [256]
    float* out = (float*)d_out;                 // [8192, 256]

    (void)in_sizes; (void)n_in; (void)out_size;
    cudaFuncSetAttribute(k_attn, cudaFuncAttributeMaxDynamicSharedMemorySize,
                         SMEM_BYTES);
    cudaFuncSetAttribute(k_h, cudaFuncAttributeMaxDynamicSharedMemorySize,
                         KH_SMEM_BYTES);

    k_cvt<<<4224, 256>>>(x, W);
    k_h<<<dim3(2, 64), 512, KH_SMEM_BYTES>>>();
    k_vec<<<2, 512>>>(W, a1, a2);
    k_f12<<<NN / 8, 256>>>(x);
    k_attn<<<dim3(2, 64), 512, SMEM_BYTES>>>(adj);
    k_out<<<(NN * DOUT) / 256, 256>>>(out);
}

// round 17
// speedup vs baseline: 1.2231x; 1.2231x over previous
#include <cuda_runtime.h>
#include <cuda_fp16.h>
#include <math.h>
#include <stdint.h>

#define NN 8192
#define DIN 512
#define DOUT 256

// ---------------- scratch (static device memory; no allocation) ----------------
__device__ __half g_xh[NN * DIN];           // x in fp16
__device__ __half g_wh[DOUT * DIN];         // W in fp16
__device__ __half g_hT[DOUT * NN];          // h transposed [n][j], fp16 (MMA B operand)
__device__ float g_b1[DIN];                 // W^T a1
__device__ float g_b2[DIN];                 // W^T a2
__device__ float g_f1[NN];
__device__ float g_f2[NN];
__device__ float g_u[NN];                   // exp(f2)
__device__ float g_v[NN];                   // exp(0.01*f2)
__device__ unsigned g_m2key;                // monotone-key max of f2
__device__ float g_O[2 * NN * DOUT];        // partial O per j-half (16 MB)
__device__ float g_l[2 * NN];               // partial softmax denominators

// ---------------- helpers ----------------
__device__ __forceinline__ float fexp(float x) {
    float j = fmaf(x, 1.4426950408889634f, 12582912.0f);
    float n = j - 12582912.0f;
    float f = fmaf(n, -0.693359375f, x);
    f = fmaf(n, 2.1219444e-4f, f);
    float r = fmaf(f, 0.041666668f, 0.16666667f);
    r = fmaf(r, f, 0.5f);
    r = fmaf(r, f, 1.0f);
    r = fmaf(r, f, 1.0f);
    int sc = __float_as_int(j) << 23;
    return __int_as_float(__float_as_int(r) + sc);
}

__device__ __forceinline__ void mma_f16(float* d, const unsigned* a,
                                        unsigned b0, unsigned b1) {
    asm volatile(
        "mma.sync.aligned.m16n8k16.row.col.f32.f16.f16.f32 "
        "{%0,%1,%2,%3}, {%4,%5,%6,%7}, {%8,%9}, {%0,%1,%2,%3};\n"
        : "+f"(d[0]), "+f"(d[1]), "+f"(d[2]), "+f"(d[3])
        : "r"(a[0]), "r"(a[1]), "r"(a[2]), "r"(a[3]), "r"(b0), "r"(b1));
}

__device__ __forceinline__ void ldsm_x4(unsigned& r0, unsigned& r1,
                                        unsigned& r2, unsigned& r3, uint32_t addr) {
    asm volatile("ldmatrix.sync.aligned.m8n8.x4.shared.b16 {%0,%1,%2,%3}, [%4];"
                 : "=r"(r0), "=r"(r1), "=r"(r2), "=r"(r3) : "r"(addr));
}

__device__ __forceinline__ void cp_async16(uint32_t saddr, const void* gptr) {
    asm volatile("cp.async.cg.shared.global [%0], [%1], 16;\n"
                 :: "r"(saddr), "l"(gptr));
}
#define CP_COMMIT() asm volatile("cp.async.commit_group;\n" ::: "memory")
#define CP_WAIT(N)  asm volatile("cp.async.wait_group %0;\n" :: "n"(N) : "memory")

__device__ __forceinline__ unsigned f2key(float x) {
    unsigned u = __float_as_uint(x);
    return ((int)u >= 0) ? (u | 0x80000000u) : ~u;
}

// ---------------- kernel 0: convert W to fp16 (x handled in k_f12) ------------
__global__ __launch_bounds__(256) void k_cvtw(const float* __restrict__ W) {
    size_t v = (size_t)blockIdx.x * 256 + threadIdx.x;   // float4 index
    float4 f = __ldg((const float4*)W + v);
    union { __half2 h[2]; uint2 u; } pk;
    pk.h[0] = __floats2half2_rn(f.x, f.y);
    pk.h[1] = __floats2half2_rn(f.z, f.w);
    *(uint2*)&g_wh[v * 4] = pk.u;
}

// ---------------- kernel 1: hT = W @ x^T via fp16 mma + cp.async pipeline -----
#define KH_S 72
#define KH_BUF (128 * KH_S)
#define KH_SMEM_BYTES (4 * KH_BUF * 2)       // 73728
__global__ __launch_bounds__(512) void k_h() {
    extern __shared__ __align__(16) __half kh_sm[];
    __half* sW = kh_sm;
    __half* sX = kh_sm + 2 * KH_BUF;
    const int tid = threadIdx.x;
    const int lane = tid & 31, w = tid >> 5;
    const int wm = w >> 2, wn = w & 3;
    const int g = lane >> 2, tq = lane & 3;
    const int n0 = blockIdx.x * 128, j0 = blockIdx.y * 128;
    const uint32_t swb = (uint32_t)__cvta_generic_to_shared(sW);
    const uint32_t sxb = (uint32_t)__cvta_generic_to_shared(sX);

    float acc[2][4][4];
#pragma unroll
    for (int mt = 0; mt < 2; mt++)
#pragma unroll
        for (int jb = 0; jb < 4; jb++)
#pragma unroll
            for (int q = 0; q < 4; q++) acc[mt][jb][q] = 0.0f;

    const int aoff = (wm * 32 + (lane & 15)) * KH_S + (lane >> 4) * 8;
    const int boff = (wn * 32 + (lane & 7) + ((lane & 16) ? 8 : 0)) * KH_S +
                     ((lane >> 3) & 1) * 8;

    auto issue = [&](int c) {
        int k0 = c * 64;
        int bsel = (c & 1) * KH_BUF;
#pragma unroll
        for (int q = 0; q < 2; q++) {
            int v = tid + q * 512;
            int r = v >> 3, ck = (v & 7) << 3;
            cp_async16(swb + (bsel + r * KH_S + ck) * 2,
                       g_wh + (size_t)(n0 + r) * DIN + k0 + ck);
            cp_async16(sxb + (bsel + r * KH_S + ck) * 2,
                       g_xh + (size_t)(j0 + r) * DIN + k0 + ck);
        }
    };

    issue(0); CP_COMMIT();
    for (int c = 0; c < 8; c++) {
        __syncthreads();
        if (c < 7) { issue(c + 1); CP_COMMIT(); }
        if (c < 7) { CP_WAIT(1); } else { CP_WAIT(0); }
        __syncthreads();
        const uint32_t aB = swb + ((c & 1) * KH_BUF + aoff) * 2;
        const uint32_t bB = sxb + ((c & 1) * KH_BUF + boff) * 2;
#pragma unroll
        for (int ks = 0; ks < 4; ks++) {
            unsigned A0[4], A1[4];
            ldsm_x4(A0[0], A0[1], A0[2], A0[3], aB + (ks * 16) * 2);
            ldsm_x4(A1[0], A1[1], A1[2], A1[3], aB + (16 * KH_S + ks * 16) * 2);
#pragma unroll
            for (int jp = 0; jp < 2; jp++) {
                unsigned B[4];
                ldsm_x4(B[0], B[1], B[2], B[3], bB + (jp * 16 * KH_S + ks * 16) * 2);
                mma_f16(acc[0][2 * jp], A0, B[0], B[1]);
                mma_f16(acc[0][2 * jp + 1], A0, B[2], B[3]);
                mma_f16(acc[1][2 * jp], A1, B[0], B[1]);
                mma_f16(acc[1][2 * jp + 1], A1, B[2], B[3]);
            }
        }
    }
#pragma unroll
    for (int mt = 0; mt < 2; mt++) {
        int n = n0 + wm * 32 + mt * 16 + g;
#pragma unroll
        for (int jb = 0; jb < 4; jb++) {
            int j = j0 + wn * 32 + jb * 8 + 2 * tq;
            *(__half2*)&g_hT[(size_t)n * NN + j] =
                __floats2half2_rn(acc[mt][jb][0], acc[mt][jb][1]);
            *(__half2*)&g_hT[(size_t)(n + 8) * NN + j] =
                __floats2half2_rn(acc[mt][jb][2], acc[mt][jb][3]);
        }
    }
}

// ---------------- kernel 2a: b1 = W^T a1, b2 = W^T a2; init m2key -------------
__global__ __launch_bounds__(512) void k_vec(const float* __restrict__ W,
                                             const float* __restrict__ a1,
                                             const float* __restrict__ a2) {
    __shared__ float as[DOUT];
    const float* a = blockIdx.x ? a2 : a1;
    float* out = blockIdx.x ? g_b2 : g_b1;
    int tid = threadIdx.x;
    if (blockIdx.x == 0 && tid == 0) g_m2key = 0u;   // reset (graph replays)
    if (tid < DOUT) as[tid] = a[tid];
    __syncthreads();
    float s = 0.0f;
#pragma unroll 16
    for (int i = 0; i < DOUT; i++)
        s = fmaf(__ldg(W + (size_t)i * DIN + tid), as[i], s);
    out[tid] = s;
}

// ---------------- kernel 2b: f1/f2 + u/v + max + x->fp16 (fused cvt) ----------
__global__ __launch_bounds__(256) void k_f12(const float* __restrict__ x) {
    __shared__ float b1s[DIN], b2s[DIN];
    __shared__ float mx[8];
    int tid = threadIdx.x;
    b1s[tid] = g_b1[tid]; b1s[tid + 256] = g_b1[tid + 256];
    b2s[tid] = g_b2[tid]; b2s[tid + 256] = g_b2[tid + 256];
    __syncthreads();
    int w = tid >> 5, lane = tid & 31;
    int row = blockIdx.x * 8 + w;
    const float* xr = x + (size_t)row * DIN;
    __half* xh = g_xh + (size_t)row * DIN;
    float s1 = 0.0f, s2 = 0.0f;
#pragma unroll
    for (int q = 0; q < 4; q++) {
        int c = q * 128 + lane * 4;
        float4 xv = __ldg((const float4*)(xr + c));
        // fused x -> fp16 conversion (x is streamed here anyway)
        union { __half2 h[2]; uint2 u; } pk;
        pk.h[0] = __floats2half2_rn(xv.x, xv.y);
        pk.h[1] = __floats2half2_rn(xv.z, xv.w);
        *(uint2*)&xh[c] = pk.u;
        s1 = fmaf(xv.x, b1s[c], fmaf(xv.y, b1s[c + 1],
             fmaf(xv.z, b1s[c + 2], fmaf(xv.w, b1s[c + 3], s1))));
        s2 = fmaf(xv.x, b2s[c], fmaf(xv.y, b2s[c + 1],
             fmaf(xv.z, b2s[c + 2], fmaf(xv.w, b2s[c + 3], s2))));
    }
#pragma unroll
    for (int off = 16; off >= 1; off >>= 1) {
        s1 += __shfl_xor_sync(0xffffffffu, s1, off);
        s2 += __shfl_xor_sync(0xffffffffu, s2, off);
    }
    if (lane == 0) {
        g_f1[row] = s1; g_f2[row] = s2;
        g_u[row] = fexp(s2);
        g_v[row] = fexp(0.01f * s2);
        mx[w] = s2;
    }
    __syncthreads();
    if (tid == 0) {
        float m = mx[0];
#pragma unroll
        for (int i = 1; i < 8; i++) m = fmaxf(m, mx[i]);
        atomicMax(&g_m2key, f2key(m));       // order-independent -> deterministic
    }
}

// ---------------- kernel 3: fused softmax-numerator @ h (R14 proven core) -----
// grid (2, 64), 512 threads, 16 warps (4m x 4n). Double-buffered sP/sHT, two
// barriers per tile; cross-warp drift overlap. Rank-1 factored P (no exp in
// hot loop), adj prefetched across the barrier into registers.
#define SPH 136
#define SP_HALFS   (128 * SPH)
#define SHT_HALFS  (256 * SPH)
#define F1_BYTEOFF (4 * SP_HALFS + 4 * SHT_HALFS)
#define SMEM_BYTES (F1_BYTEOFF + 3 * 512 + 128)
__global__ __launch_bounds__(512, 1) void k_attn(const float* __restrict__ adj) {
    extern __shared__ __align__(16) __half smh[];
    float* f1s = (float*)((char*)smh + F1_BYTEOFF);
    float* sA  = f1s + 128;
    float* sB  = f1s + 256;

    const int tid = threadIdx.x;
    const int jh = blockIdx.x, rb = blockIdx.y;
    const int lane = tid & 31, w = tid >> 5;
    const int wm = w >> 2, wn = w & 3;
    const int g = lane >> 2, tq = lane & 3;

    unsigned mk = g_m2key;
    const float m2 = (mk & 0x80000000u) ? __uint_as_float(mk & 0x7FFFFFFFu)
                                        : __uint_as_float(~mk);
    if (tid < 128) {
        float f1 = g_f1[rb * 128 + tid];
        float zc = f1 + m2;
        float c = fmaxf(zc, 0.01f * zc);     // row shift (same both halves)
        f1s[tid] = f1;
        sA[tid] = fexp(f1 - c);
        sB[tid] = fexp(fmaf(0.01f, f1, -c));
    }
    __syncthreads();

    float acc[2][8][4];
#pragma unroll
    for (int mt = 0; mt < 2; mt++)
#pragma unroll
        for (int nb = 0; nb < 8; nb++)
#pragma unroll
            for (int q = 0; q < 4; q++) acc[mt][nb][q] = 0.0f;

    float lacc[8];
#pragma unroll
    for (int i = 0; i < 8; i++) lacc[i] = 0.0f;

    const float* adjb = adj + (size_t)(rb * 128) * NN;
    const uint32_t smbase = (uint32_t)__cvta_generic_to_shared(smh);

    const int aoff = (wm * 32 + (lane & 15)) * SPH + (lane >> 4) * 8;
    const int boff = (wn * 64 + (lane & 7) + ((lane & 16) ? 8 : 0)) * SPH +
                     ((lane >> 3) & 1) * 8;

    // preload adj for tile 0
    float4 avp[8];
    {
        const int j0 = jh * 4096;
#pragma unroll
        for (int i = 0; i < 8; i++)
            avp[i] = __ldg((const float4*)(adjb + (size_t)(w + 16 * i) * NN + j0 + 4 * lane));
    }

    for (int jt = 0; jt < 32; jt++) {
        const int b = jt & 1;
        const int j0 = jh * 4096 + jt * 128;
        __half* sP = smh + b * SP_HALFS;
        const uint32_t sht_b = smbase + (2 * SP_HALFS + b * SHT_HALFS) * 2;

        // ---- stage H tile via cp.async ----
        {
            const __half* hsrc = g_hT + j0;
#pragma unroll
            for (int i = 0; i < 8; i++) {
                int v = tid + i * 512;
                int n = v >> 4;
                int c = (v & 15) << 3;
                cp_async16(sht_b + (n * SPH + c) * 2, hsrc + (size_t)n * NN + c);
            }
            CP_COMMIT();
        }

        // ---- P tile from rank-1 factors (no exp) ----
        float4 f2v = __ldg((const float4*)(g_f2 + j0 + 4 * lane));
        float4 uv  = __ldg((const float4*)(g_u  + j0 + 4 * lane));
        float4 vv  = __ldg((const float4*)(g_v  + j0 + 4 * lane));
#pragma unroll
        for (int i = 0; i < 8; i++) {
            int r = w + 16 * i;
            float f1v = f1s[r], ai = sA[r], bi = sB[r];
            float p0 = ((f1v + f2v.x >= 0.0f) ? ai * uv.x : bi * vv.x) * avp[i].x;
            float p1 = ((f1v + f2v.y >= 0.0f) ? ai * uv.y : bi * vv.y) * avp[i].y;
            float p2 = ((f1v + f2v.z >= 0.0f) ? ai * uv.z : bi * vv.z) * avp[i].z;
            float p3 = ((f1v + f2v.w >= 0.0f) ? ai * uv.w : bi * vv.w) * avp[i].w;
            __half2 h01 = __floats2half2_rn(p0, p1);
            __half2 h23 = __floats2half2_rn(p2, p3);
            union { __half2 h2[2]; uint2 u; } pk;
            pk.h2[0] = h01; pk.h2[1] = h23;
            *(uint2*)&sP[r * SPH + 4 * lane] = pk.u;
            float2 q01 = __half22float2(h01);    // sum fp16-ROUNDED values
            float2 q23 = __half22float2(h23);
            lacc[i] += (q01.x + q01.y) + (q23.x + q23.y);
        }

        // ---- prefetch adj for next tile (hides DRAM latency behind MMA) ----
        {
            const int jtn = (jt < 31) ? jt + 1 : 31;
            const int j0n = jh * 4096 + jtn * 128;
#pragma unroll
            for (int i = 0; i < 8; i++)
                avp[i] = __ldg((const float4*)(adjb + (size_t)(w + 16 * i) * NN + j0n + 4 * lane));
        }
        CP_WAIT(0);
        __syncthreads();

        // ---- mma via ldmatrix.x4: acc += P[128x128] @ H[128x256] ----
        const uint32_t aB = smbase + (b * SP_HALFS + aoff) * 2;
        const uint32_t bB = smbase + (2 * SP_HALFS + b * SHT_HALFS + boff) * 2;
#pragma unroll
        for (int kc = 0; kc < 8; kc++) {
            unsigned A0[4], A1[4];
            ldsm_x4(A0[0], A0[1], A0[2], A0[3], aB + (kc * 16) * 2);
            ldsm_x4(A1[0], A1[1], A1[2], A1[3], aB + (16 * SPH + kc * 16) * 2);
#pragma unroll
            for (int np = 0; np < 4; np++) {
                unsigned B[4];
                ldsm_x4(B[0], B[1], B[2], B[3], bB + (np * 16 * SPH + kc * 16) * 2);
                mma_f16(acc[0][2 * np], A0, B[0], B[1]);
                mma_f16(acc[0][2 * np + 1], A0, B[2], B[3]);
                mma_f16(acc[1][2 * np], A1, B[0], B[1]);
                mma_f16(acc[1][2 * np + 1], A1, B[2], B[3]);
            }
        }
    }

    // ---- final row-sum reduce + store partial l ----
#pragma unroll
    for (int i = 0; i < 8; i++) {
        float s = lacc[i];
#pragma unroll
        for (int off = 16; off >= 1; off >>= 1)
            s += __shfl_xor_sync(0xffffffffu, s, off);
        if (lane == 0) g_l[jh * NN + rb * 128 + w + 16 * i] = s;
    }

    // ---- epilogue: partial O ----
    float* Op = g_O + (size_t)jh * NN * DOUT;
#pragma unroll
    for (int mt = 0; mt < 2; mt++) {
        int row0 = rb * 128 + wm * 32 + mt * 16 + g;
#pragma unroll
        for (int nb = 0; nb < 8; nb++) {
            int col = wn * 64 + nb * 8 + tq * 2;
            *(float2*)&Op[(size_t)row0 * DOUT + col] =
                make_float2(acc[mt][nb][0], acc[mt][nb][1]);
            *(float2*)&Op[(size_t)(row0 + 8) * DOUT + col] =
                make_float2(acc[mt][nb][2], acc[mt][nb][3]);
        }
    }
}

// ---------------- kernel 4: combine halves, divide, elu (vectorized) ----------
__global__ __launch_bounds__(512) void k_out(float* __restrict__ out) {
    int v = blockIdx.x * 512 + threadIdx.x;     // float4 index, 0 .. 512K-1
    int row = v >> 6;                            // 64 float4 per row
    float linv = 1.0f / (g_l[row] + g_l[NN + row]);
    float4 o0 = *(const float4*)&g_O[(size_t)v * 4];
    float4 o1 = *(const float4*)&g_O[NN * DOUT + (size_t)v * 4];
    float4 r;
    r.x = (o0.x + o1.x) * linv;
    r.y = (o0.y + o1.y) * linv;
    r.z = (o0.z + o1.z) * linv;
    r.w = (o0.w + o1.w) * linv;
    r.x = (r.x > 0.0f) ? r.x : expm1f(r.x);
    r.y = (r.y > 0.0f) ? r.y : expm1f(r.y);
    r.z = (r.z > 0.0f) ? r.z : expm1f(r.z);
    r.w = (r.w > 0.0f) ? r.w : expm1f(r.w);
    *(float4*)&out[(size_t)v * 4] = r;
}

// ---------------- launch ----------------
extern "C" void kernel_launch(void* const* d_in, const int* in_sizes, int n_in,
                              void* d_out, int out_size) {
    const float* x   = (const float*)d_in[0];   // [8192, 512]
    const float* adj = (const float*)d_in[1];   // [8192, 8192]
    const float* W   = (const float*)d_in[2];   // [256, 512]
    const float* a1  = (const float*)d_in[3];   // [256]
    const float* a2  = (const float*)d_in[4];   // [256]
    float* out = (float*)d_out;                 // [8192, 256]

    (void)in_sizes; (void)n_in; (void)out_size;
    cudaFuncSetAttribute(k_attn, cudaFuncAttributeMaxDynamicSharedMemorySize,
                         SMEM_BYTES);
    cudaFuncSetAttribute(k_h, cudaFuncAttributeMaxDynamicSharedMemorySize,
                         KH_SMEM_BYTES);

    k_vec<<<2, 512>>>(W, a1, a2);
    k_f12<<<NN / 8, 256>>>(x);                  // also converts x -> fp16
    k_cvtw<<<(DOUT * DIN / 4) / 256, 256>>>(W); // W -> fp16 (512 KB)
    k_h<<<dim3(2, 64), 512, KH_SMEM_BYTES>>>();
    k_attn<<<dim3(2, 64), 512, SMEM_BYTES>>>(adj);
    k_out<<<(NN * DOUT / 4) / 512, 512>>>(out);
}